// round 15
// baseline (speedup 1.0000x reference)
#include <cuda_runtime.h>
#include <cuda_bf16.h>
#include <cuda_fp16.h>
#include <mma.h>
#include <cstdint>
#include <math.h>

using namespace nvcuda;

// Problem shape: B=8192, H=512, M=4096, D=256, k<=32
#define BN 8192
#define MN 4096
#define DN 256
#define MAXK 32
#define NCAND 32
#define RPB 4           // rows per topk block
#define CAPB 64         // candidate window [NCAND, CAPB]
#define BIGF 3.0e37f

__device__ float g_q[BN * DN];               // exact-grade fp32 q (for rescore)
__device__ __nv_bfloat16 g_qb[BN * DN];      // bf16 q (for WMMA)
__device__ __nv_bfloat16 g_mb[MN * DN];      // bf16 mem (for WMMA)
__device__ float g_msq[MN];                  // exact ||m||^2
__device__ __half g_dist[(size_t)BN * MN];   // 67MB approx dists (selection only)

// ---------------------------------------------------------------------------
// Kernel 1: q = h @ Wq + bq via 3xTF32 tensor-core GEMM (fp32-equivalent:
// Ahi*Bhi + Ahi*Blo + Alo*Bhi; dropped lo*lo term ~2^-22 relative).
// CTA 128x128, 8 warps (2x4), warp 64x32. K in chunks of 16 (2 k8-steps).
// ---------------------------------------------------------------------------
#define QSA 20          // A smem stride (floats)
#define QSB 132         // B smem stride (floats)

__global__ __launch_bounds__(256, 2)
void qproj_kernel(const float* __restrict__ Hm, const float* __restrict__ Wq,
                  const float* __restrict__ bq, int B, int Hd, int D) {
    __shared__ float Ahi[128 * QSA], Alo[128 * QSA];   // 2 x 10240 B
    __shared__ float Bhi[16 * QSB], Blo[16 * QSB];     // 2 x 8448 B
    __shared__ float bq_s[128];
    const int tid = threadIdx.x, lane = tid & 31, wid = tid >> 5;
    const int warp_m = wid >> 2, warp_n = wid & 3;     // 2 x 4
    const int brow = blockIdx.y * 128, bcol = blockIdx.x * 128;

    if (tid < 128) bq_s[tid] = bq[bcol + tid];

    const int ra = tid >> 1, ka = (tid & 1) * 8;       // A loader: 128r x 16k
    const int krow = tid >> 4, cb = (tid & 15) * 8;    // B loader: 16k x 128c

    wmma::fragment<wmma::accumulator, 16, 16, 8, float> acc[4][2];
#pragma unroll
    for (int mt = 0; mt < 4; mt++)
#pragma unroll
        for (int nt = 0; nt < 2; nt++) wmma::fill_fragment(acc[mt][nt], 0.f);

    const int nchunk = Hd / 16;
    float4 a0, a1, b0, b1;
    a0 = *(const float4*)(Hm + (size_t)(brow + ra) * Hd + ka);
    a1 = *(const float4*)(Hm + (size_t)(brow + ra) * Hd + ka + 4);
    b0 = *(const float4*)(Wq + (size_t)krow * D + bcol + cb);
    b1 = *(const float4*)(Wq + (size_t)krow * D + bcol + cb + 4);

    for (int kc = 0; kc < nchunk; kc++) {
        // split-store prefetched regs into smem (hi = tf32(x), lo = tf32(x-hi))
        {
            float av[8] = {a0.x, a0.y, a0.z, a0.w, a1.x, a1.y, a1.z, a1.w};
            float bv[8] = {b0.x, b0.y, b0.z, b0.w, b1.x, b1.y, b1.z, b1.w};
#pragma unroll
            for (int e = 0; e < 8; e++) {
                float hi = wmma::__float_to_tf32(av[e]);
                Ahi[ra * QSA + ka + e] = hi;
                Alo[ra * QSA + ka + e] = wmma::__float_to_tf32(av[e] - hi);
            }
#pragma unroll
            for (int e = 0; e < 8; e++) {
                float hi = wmma::__float_to_tf32(bv[e]);
                Bhi[krow * QSB + cb + e] = hi;
                Blo[krow * QSB + cb + e] = wmma::__float_to_tf32(bv[e] - hi);
            }
        }
        if (kc + 1 < nchunk) {
            int k0 = (kc + 1) * 16;
            a0 = *(const float4*)(Hm + (size_t)(brow + ra) * Hd + k0 + ka);
            a1 = *(const float4*)(Hm + (size_t)(brow + ra) * Hd + k0 + ka + 4);
            b0 = *(const float4*)(Wq + (size_t)(k0 + krow) * D + bcol + cb);
            b1 = *(const float4*)(Wq + (size_t)(k0 + krow) * D + bcol + cb + 4);
        }
        __syncthreads();

#pragma unroll
        for (int ks = 0; ks < 2; ks++) {
            wmma::fragment<wmma::matrix_b, 16, 16, 8, wmma::precision::tf32, wmma::row_major> fbh[2], fbl[2];
#pragma unroll
            for (int nt = 0; nt < 2; nt++) {
                wmma::load_matrix_sync(fbh[nt], Bhi + ks * 8 * QSB + warp_n * 32 + nt * 16, QSB);
                wmma::load_matrix_sync(fbl[nt], Blo + ks * 8 * QSB + warp_n * 32 + nt * 16, QSB);
            }
#pragma unroll
            for (int mt = 0; mt < 4; mt++) {
                wmma::fragment<wmma::matrix_a, 16, 16, 8, wmma::precision::tf32, wmma::row_major> fah, fal;
                wmma::load_matrix_sync(fah, Ahi + (warp_m * 64 + mt * 16) * QSA + ks * 8, QSA);
                wmma::load_matrix_sync(fal, Alo + (warp_m * 64 + mt * 16) * QSA + ks * 8, QSA);
#pragma unroll
                for (int nt = 0; nt < 2; nt++) {
                    wmma::mma_sync(acc[mt][nt], fah, fbh[nt], acc[mt][nt]);
                    wmma::mma_sync(acc[mt][nt], fah, fbl[nt], acc[mt][nt]);
                    wmma::mma_sync(acc[mt][nt], fal, fbh[nt], acc[mt][nt]);
                }
            }
        }
        __syncthreads();
    }

    // epilogue: add bias, write fp32 q + bf16 q (staging aliases Ahi)
    float* eb = Ahi + wid * 256;
    const int er = lane >> 1, ec = (lane & 1) * 8;
#pragma unroll
    for (int mt = 0; mt < 4; mt++) {
#pragma unroll
        for (int nt = 0; nt < 2; nt++) {
            wmma::store_matrix_sync(eb, acc[mt][nt], 16, wmma::mem_row_major);
            __syncwarp();
            int grow = brow + warp_m * 64 + mt * 16 + er;
            int cl = warp_n * 32 + nt * 16 + ec;
            const float* e = eb + er * 16 + ec;
            float o[8];
#pragma unroll
            for (int u = 0; u < 8; u++) o[u] = e[u] + bq_s[cl + u];
            *(float4*)&g_q[(size_t)grow * D + bcol + cl] = make_float4(o[0], o[1], o[2], o[3]);
            *(float4*)&g_q[(size_t)grow * D + bcol + cl + 4] = make_float4(o[4], o[5], o[6], o[7]);
            __nv_bfloat162 p0 = __float22bfloat162_rn(make_float2(o[0], o[1]));
            __nv_bfloat162 p1 = __float22bfloat162_rn(make_float2(o[2], o[3]));
            __nv_bfloat162 p2 = __float22bfloat162_rn(make_float2(o[4], o[5]));
            __nv_bfloat162 p3 = __float22bfloat162_rn(make_float2(o[6], o[7]));
            uint4 pk;
            pk.x = *(uint32_t*)&p0; pk.y = *(uint32_t*)&p1;
            pk.z = *(uint32_t*)&p2; pk.w = *(uint32_t*)&p3;
            *(uint4*)&g_qb[(size_t)grow * D + bcol + cl] = pk;
            __syncwarp();
        }
    }
}

// ---------------------------------------------------------------------------
// msq (exact fp32) + bf16 copy of mem
// ---------------------------------------------------------------------------
__global__ void msq_kernel(const float* __restrict__ Mem, int D) {
    const int r = blockIdx.x;
    const float4* p = (const float4*)(Mem + (size_t)r * D);
    float s = 0.f;
    for (int i = threadIdx.x; i < D / 4; i += 64) {
        float4 v = p[i];
        s += v.x * v.x + v.y * v.y + v.z * v.z + v.w * v.w;
        __nv_bfloat162 p0 = __float22bfloat162_rn(make_float2(v.x, v.y));
        __nv_bfloat162 p1 = __float22bfloat162_rn(make_float2(v.z, v.w));
        uint2 pk; pk.x = *(uint32_t*)&p0; pk.y = *(uint32_t*)&p1;
        *(uint2*)&g_mb[(size_t)r * D + i * 4] = pk;
    }
#pragma unroll
    for (int off = 16; off; off >>= 1) s += __shfl_down_sync(0xffffffffu, s, off);
    __shared__ float ws[2];
    if ((threadIdx.x & 31) == 0) ws[threadIdx.x >> 5] = s;
    __syncthreads();
    if (threadIdx.x == 0) g_msq[r] = ws[0] + ws[1];
}

// ---------------------------------------------------------------------------
// Kernel 3: dist = msq[m] - 2*(q.m) via WMMA bf16, DOUBLE-BUFFERED smem.
// (unchanged from the 275us kernel)
// ---------------------------------------------------------------------------
#define ASTRIDE 40
#define STAGE_BYTES 20480

__global__ __launch_bounds__(256, 2)
void dist_wmma_kernel(int B, int M, int D) {
    __shared__ __align__(16) char sbuf[2 * STAGE_BYTES];
    __shared__ float msq_s[128];
    const int tid = threadIdx.x;
    const int lane = tid & 31, wid = tid >> 5;
    const int warp_m = wid >> 2, warp_n = wid & 3;
    const int brow = blockIdx.y * 128;
    const int bcol = blockIdx.x * 128;

    if (tid < 128) msq_s[tid] = g_msq[bcol + tid];

    const __nv_bfloat16* Ag = g_qb + (size_t)brow * DN;
    const __nv_bfloat16* Bg = g_mb + (size_t)bcol * DN;

    const int r0 = tid >> 2, q0 = (tid & 3) * 8;
    const int r1 = r0 + 64, q1 = q0;

    uint4 ra0, ra1, rb0, rb1;
    ra0 = *(const uint4*)(Ag + (size_t)r0 * DN + q0);
    ra1 = *(const uint4*)(Ag + (size_t)r1 * DN + q1);
    rb0 = *(const uint4*)(Bg + (size_t)r0 * DN + q0);
    rb1 = *(const uint4*)(Bg + (size_t)r1 * DN + q1);

    wmma::fragment<wmma::accumulator, 16, 16, 16, float> acc[4][2];
#pragma unroll
    for (int mt = 0; mt < 4; mt++)
#pragma unroll
        for (int nt = 0; nt < 2; nt++) wmma::fill_fragment(acc[mt][nt], 0.f);

    {
        __nv_bfloat16* As0 = (__nv_bfloat16*)sbuf;
        __nv_bfloat16* Bs0 = (__nv_bfloat16*)(sbuf + 10240);
        *(uint4*)(As0 + r0 * ASTRIDE + q0) = ra0;
        *(uint4*)(As0 + r1 * ASTRIDE + q1) = ra1;
        *(uint4*)(Bs0 + r0 * ASTRIDE + q0) = rb0;
        *(uint4*)(Bs0 + r1 * ASTRIDE + q1) = rb1;
    }
    __syncthreads();

    for (int c = 0; c < 8; c++) {
        const int st = c & 1;
        const __nv_bfloat16* As = (const __nv_bfloat16*)(sbuf + st * STAGE_BYTES);
        const __nv_bfloat16* Bs = As + 10240 / 2;

        if (c < 7) {
            int kb = (c + 1) * 32;
            ra0 = *(const uint4*)(Ag + (size_t)r0 * DN + kb + q0);
            ra1 = *(const uint4*)(Ag + (size_t)r1 * DN + kb + q1);
            rb0 = *(const uint4*)(Bg + (size_t)r0 * DN + kb + q0);
            rb1 = *(const uint4*)(Bg + (size_t)r1 * DN + kb + q1);
        }

#pragma unroll
        for (int ks = 0; ks < 2; ks++) {
            wmma::fragment<wmma::matrix_b, 16, 16, 16, __nv_bfloat16, wmma::col_major> bf[2];
#pragma unroll
            for (int nt = 0; nt < 2; nt++)
                wmma::load_matrix_sync(bf[nt],
                    Bs + (warp_n * 32 + nt * 16) * ASTRIDE + ks * 16, ASTRIDE);
#pragma unroll
            for (int mt = 0; mt < 4; mt++) {
                wmma::fragment<wmma::matrix_a, 16, 16, 16, __nv_bfloat16, wmma::row_major> af;
                wmma::load_matrix_sync(af,
                    As + (warp_m * 64 + mt * 16) * ASTRIDE + ks * 16, ASTRIDE);
#pragma unroll
                for (int nt = 0; nt < 2; nt++)
                    wmma::mma_sync(acc[mt][nt], af, bf[nt], acc[mt][nt]);
            }
        }

        if (c < 7) {
            const int nst = (c + 1) & 1;
            __nv_bfloat16* Asn = (__nv_bfloat16*)(sbuf + nst * STAGE_BYTES);
            __nv_bfloat16* Bsn = Asn + 10240 / 2;
            *(uint4*)(Asn + r0 * ASTRIDE + q0) = ra0;
            *(uint4*)(Asn + r1 * ASTRIDE + q1) = ra1;
            *(uint4*)(Bsn + r0 * ASTRIDE + q0) = rb0;
            *(uint4*)(Bsn + r1 * ASTRIDE + q1) = rb1;
        }
        __syncthreads();
    }

    float* ebuf = (float*)sbuf;
    float* eb = ebuf + wid * 256;
    const int er = lane >> 1, ec = (lane & 1) * 8;
#pragma unroll
    for (int mt = 0; mt < 4; mt++) {
#pragma unroll
        for (int nt = 0; nt < 2; nt++) {
            wmma::store_matrix_sync(eb, acc[mt][nt], 16, wmma::mem_row_major);
            __syncwarp();
            int grow = brow + warp_m * 64 + mt * 16 + er;
            int cl = warp_n * 32 + nt * 16 + ec;
            const float* e = eb + er * 16 + ec;
            __half2 h0 = __floats2half2_rn(msq_s[cl + 0] - 2.f * e[0],
                                           msq_s[cl + 1] - 2.f * e[1]);
            __half2 h1 = __floats2half2_rn(msq_s[cl + 2] - 2.f * e[2],
                                           msq_s[cl + 3] - 2.f * e[3]);
            __half2 h2 = __floats2half2_rn(msq_s[cl + 4] - 2.f * e[4],
                                           msq_s[cl + 5] - 2.f * e[5]);
            __half2 h3 = __floats2half2_rn(msq_s[cl + 6] - 2.f * e[6],
                                           msq_s[cl + 7] - 2.f * e[7]);
            uint4 pk;
            pk.x = *(uint32_t*)&h0; pk.y = *(uint32_t*)&h1;
            pk.z = *(uint32_t*)&h2; pk.w = *(uint32_t*)&h3;
            *(uint4*)&g_dist[(size_t)grow * M + bcol + cl] = pk;
            __syncwarp();
        }
    }
}

// ---------------------------------------------------------------------------
// Kernel 4: warp-per-row. Stats -> BISECTED threshold filter to cnt in
// [32,64] (indices only; set threshold-defined -> deterministic) -> rescore
// ALL candidates exactly (coalesced, batched) -> exact top-k over 64 with
// value+index tiebreak -> softmax -> gather. No per-key selection loop.
// ---------------------------------------------------------------------------
__global__ __launch_bounds__(128)
void topk_kernel(const float* __restrict__ Mem, const int* __restrict__ kp,
                 float* __restrict__ out, int M, int D) {
    __shared__ float sh_q[RPB * DN];
    __shared__ int cidx[RPB][CAPB];
    __shared__ float cd[RPB][CAPB];
    __shared__ int ccnt[RPB];
    __shared__ float swt[RPB][MAXK];
    __shared__ int ssel[RPB][MAXK];

    const int tid = threadIdx.x, lane = tid & 31, w = tid >> 5;
    const int b0 = blockIdx.x * RPB;
    int k = kp[0];
    if (k < 1) k = 1;
    if (k > MAXK) k = MAXK;

    {
        const float4* qsrc = (const float4*)(g_q + (size_t)b0 * DN);
        float4* qdst = (float4*)sh_q;
        for (int i = tid; i < RPB * DN / 4; i += 128) qdst[i] = qsrc[i];
    }
    __syncthreads();

    const uint4* drow4 = (const uint4*)(g_dist + (size_t)(b0 + w) * MN);

    // Phase B: stats over 256 samples -> mu, sigma
    float s1 = 0.f, s2 = 0.f;
    {
        uint4 pk = drow4[lane];
        const __half2* hp = (const __half2*)&pk;
#pragma unroll
        for (int e = 0; e < 4; e++) {
            float2 f = __half22float2(hp[e]);
            s1 += f.x + f.y; s2 += f.x * f.x + f.y * f.y;
        }
    }
#pragma unroll
    for (int off = 16; off; off >>= 1) {
        s1 += __shfl_xor_sync(0xffffffffu, s1, off);
        s2 += __shfl_xor_sync(0xffffffffu, s2, off);
    }
    float mu = s1 * (1.f / 256.f);
    float sg = sqrtf(fmaxf(s2 * (1.f / 256.f) - mu * mu, 0.f));
    sg = fmaxf(sg, fabsf(mu) * 1e-4f + 1e-6f);

    // Phase C: bisect threshold until cnt in [NCAND, CAPB]
    float tlo = mu - 4.f * sg, thi = mu;
    float thr = mu - 2.3f * sg;
    int cnt = 0;
    for (int attempt = 0; attempt < 16; attempt++) {
        __half thrh = __float2half_ru(thr);
        if (lane == 0) ccnt[w] = 0;
        __syncwarp();
#pragma unroll 8
        for (int j = 0; j < 16; j++) {
            int gi = j * 32 + lane;
            uint4 pk = drow4[gi];
            __half2 a = *(__half2*)&pk.x, b = *(__half2*)&pk.y;
            __half2 c2 = *(__half2*)&pk.z, d2 = *(__half2*)&pk.w;
            __half2 m2 = __hmin2(__hmin2(a, b), __hmin2(c2, d2));
            __half mn = __hmin(__low2half(m2), __high2half(m2));
            if (__hlt(mn, thrh)) {
                const __half* hp = (const __half*)&pk;
                int base = gi * 8;
#pragma unroll
                for (int e = 0; e < 8; e++) {
                    if (__hlt(hp[e], thrh)) {
                        int pos = atomicAdd(&ccnt[w], 1);
                        if (pos < CAPB) cidx[w][pos] = base + e;
                    }
                }
            }
        }
        __syncwarp();
        cnt = ccnt[w];
        if (cnt >= NCAND && cnt <= CAPB) break;
        if (cnt < NCAND) tlo = thr; else thi = thr;
        thr = 0.5f * (tlo + thi);
        __syncwarp();
    }
    if (cnt > CAPB) cnt = CAPB;

    // Phase E: exact rescore of ALL candidates (coalesced, 8 per batch)
    {
        const float4* qp = (const float4*)(sh_q + w * DN);
        const float4 qa = qp[lane * 2], qb2 = qp[lane * 2 + 1];
        for (int cbn = 0; cbn < CAPB; cbn += 8) {
            if (cbn >= cnt) break;
            float4 ma[8], mb[8];
            int mi[8];
#pragma unroll
            for (int u = 0; u < 8; u++) {
                int slot = cbn + u;
                mi[u] = cidx[w][(slot < cnt) ? slot : 0];
                const float4* mp = (const float4*)(Mem + (size_t)mi[u] * DN);
                ma[u] = mp[lane * 2];
                mb[u] = mp[lane * 2 + 1];
            }
            float dots[8];
#pragma unroll
            for (int u = 0; u < 8; u++)
                dots[u] = qa.x * ma[u].x + qa.y * ma[u].y + qa.z * ma[u].z + qa.w * ma[u].w
                        + qb2.x * mb[u].x + qb2.y * mb[u].y + qb2.z * mb[u].z + qb2.w * mb[u].w;
#pragma unroll
            for (int off = 16; off; off >>= 1)
#pragma unroll
                for (int u = 0; u < 8; u++)
                    dots[u] += __shfl_xor_sync(0xffffffffu, dots[u], off);
            if (lane == 0) {
#pragma unroll
                for (int u = 0; u < 8; u++)
                    cd[w][cbn + u] = g_msq[mi[u]] - 2.f * dots[u];
            }
        }
    }
    __syncwarp();

    // Phase F: exact top-k over <=64 (2 slots/lane), value+index tiebreak
    {
        float v0 = (lane < cnt) ? cd[w][lane] : BIGF;
        int i0 = (lane < cnt) ? cidx[w][lane] : 0x7FFFFFFF;
        float v1 = (lane + 32 < cnt) ? cd[w][lane + 32] : BIGF;
        int i1 = (lane + 32 < cnt) ? cidx[w][lane + 32] : 0x7FFFFFFF;

        for (int it = 0; it < k; it++) {
            float m; int mi;
            if (v1 < v0 || (v1 == v0 && i1 < i0)) { m = v1; mi = i1; }
            else                                   { m = v0; mi = i0; }
#pragma unroll
            for (int off = 16; off; off >>= 1) {
                float m2 = __shfl_xor_sync(0xffffffffu, m, off);
                int mi2 = __shfl_xor_sync(0xffffffffu, mi, off);
                if (m2 < m || (m2 == m && mi2 < mi)) { m = m2; mi = mi2; }
            }
            if (lane == 0) { swt[w][it] = m; ssel[w][it] = mi; }
            if (i0 == mi) { v0 = BIGF; i0 = 0x7FFFFFFF; }
            if (i1 == mi) { v1 = BIGF; i1 = 0x7FFFFFFF; }
        }
        __syncwarp();
        if (lane == 0) {
            float d0 = swt[w][0], ssum = 0.f;
            for (int i = 0; i < k; i++) {
                float e = expf(d0 - swt[w][i]);
                swt[w][i] = e; ssum += e;
            }
            float inv = 1.f / ssum;
            for (int i = 0; i < k; i++) swt[w][i] *= inv;
        }
        __syncwarp();

        const int d0c = lane * 8;
        float acc[8];
#pragma unroll
        for (int e = 0; e < 8; e++) acc[e] = 0.f;
#pragma unroll 4
        for (int i = 0; i < k; i++) {
            float wt = swt[w][i];
            const float4* mp = (const float4*)(Mem + (size_t)ssel[w][i] * DN + d0c);
            float4 a = mp[0], bb = mp[1];
            acc[0] += wt * a.x;  acc[1] += wt * a.y;
            acc[2] += wt * a.z;  acc[3] += wt * a.w;
            acc[4] += wt * bb.x; acc[5] += wt * bb.y;
            acc[6] += wt * bb.z; acc[7] += wt * bb.w;
        }
        *(float4*)&out[(size_t)(b0 + w) * DN + d0c] =
            make_float4(acc[0], acc[1], acc[2], acc[3]);
        *(float4*)&out[(size_t)(b0 + w) * DN + d0c + 4] =
            make_float4(acc[4], acc[5], acc[6], acc[7]);
    }
}

// ---------------------------------------------------------------------------
extern "C" void kernel_launch(void* const* d_in, const int* in_sizes, int n_in,
                              void* d_out, int out_size) {
    const float* h   = (const float*)d_in[0];
    const float* mem = (const float*)d_in[1];
    const float* Wq  = (const float*)d_in[2];
    const float* bq  = (const float*)d_in[3];
    const int*   kp  = (const int*)d_in[4];
    float* out = (float*)d_out;

    const int D  = in_sizes[3];
    const int Hd = in_sizes[2] / D;
    const int B  = in_sizes[0] / Hd;
    const int M  = in_sizes[1] / D;

    dim3 g1(D / 128, B / 128);
    qproj_kernel<<<g1, 256>>>(h, Wq, bq, B, Hd, D);
    msq_kernel<<<M, 64>>>(mem, D);
    dim3 g3(M / 128, B / 128);
    dist_wmma_kernel<<<g3, 256>>>(B, M, D);
    topk_kernel<<<B / RPB, 128>>>(mem, kp, out, M, D);
}

// round 16
// speedup vs baseline: 1.2761x; 1.2761x over previous
#include <cuda_runtime.h>
#include <cuda_bf16.h>
#include <cuda_fp16.h>
#include <mma.h>
#include <cstdint>
#include <math.h>

using namespace nvcuda;

// Problem shape: B=8192, H=512, M=4096, D=256, k<=32
#define BN 8192
#define MN 4096
#define DN 256
#define MAXK 32
#define NCAND 32
#define RPB 8           // rows per topk block (8 warps)
#define CAPB 512        // candidate slots per row
#define BIGF 3.0e37f

__device__ float g_q[BN * DN];               // exact fp32 q (for rescore)
__device__ __nv_bfloat16 g_qb[BN * DN];      // bf16 q (for WMMA)
__device__ __nv_bfloat16 g_mb[MN * DN];      // bf16 mem (for WMMA)
__device__ float g_msq[MN];                  // exact ||m||^2
__device__ __half g_dist[(size_t)BN * MN];   // 67MB approx dists (selection only)

// ---------------------------------------------------------------------------
// Kernel 1: q = h @ Wq + bq  (exact fp32 SGEMM) + bf16 copy of q
// ---------------------------------------------------------------------------
__global__ __launch_bounds__(256, 2)
void qproj_kernel(const float* __restrict__ Hm, const float* __restrict__ Wq,
                  const float* __restrict__ bq, int B, int Hd, int D) {
    __shared__ float As[8][128];
    __shared__ float Bs[8][128];
    const int tid = threadIdx.x;
    const int brow = blockIdx.y * 128, bcol = blockIdx.x * 128;
    const int tx = tid & 15, ty = tid >> 4;
    const int a_row = tid >> 1, a_k = (tid & 1) * 4;
    const int b_k = tid >> 5, b_c = (tid & 31) * 4;
    const float* Ap = Hm + (size_t)(brow + a_row) * Hd + a_k;
    const float* Bp = Wq + (size_t)b_k * D + bcol + b_c;
    float acc[8][8];
#pragma unroll
    for (int i = 0; i < 8; i++)
#pragma unroll
        for (int j = 0; j < 8; j++) acc[i][j] = 0.f;
    for (int k0 = 0; k0 < Hd; k0 += 8) {
        float4 av = *(const float4*)(Ap + k0);
        float4 bv = *(const float4*)(Bp + (size_t)k0 * D);
        __syncthreads();
        As[a_k + 0][a_row] = av.x; As[a_k + 1][a_row] = av.y;
        As[a_k + 2][a_row] = av.z; As[a_k + 3][a_row] = av.w;
        *(float4*)&Bs[b_k][b_c] = bv;
        __syncthreads();
#pragma unroll
        for (int kk = 0; kk < 8; kk++) {
            float ar[8], br[8];
            *(float4*)&ar[0] = *(const float4*)&As[kk][ty * 8];
            *(float4*)&ar[4] = *(const float4*)&As[kk][ty * 8 + 4];
            *(float4*)&br[0] = *(const float4*)&Bs[kk][tx * 8];
            *(float4*)&br[4] = *(const float4*)&Bs[kk][tx * 8 + 4];
#pragma unroll
            for (int i = 0; i < 8; i++)
#pragma unroll
                for (int j = 0; j < 8; j++) acc[i][j] += ar[i] * br[j];
        }
    }
#pragma unroll
    for (int i = 0; i < 8; i++) {
        int r = brow + ty * 8 + i;
#pragma unroll
        for (int j = 0; j < 8; j += 4) {
            int c = bcol + tx * 8 + j;
            float4 o;
            o.x = acc[i][j + 0] + bq[c + 0];
            o.y = acc[i][j + 1] + bq[c + 1];
            o.z = acc[i][j + 2] + bq[c + 2];
            o.w = acc[i][j + 3] + bq[c + 3];
            *(float4*)&g_q[(size_t)r * D + c] = o;
            __nv_bfloat162 p0 = __float22bfloat162_rn(make_float2(o.x, o.y));
            __nv_bfloat162 p1 = __float22bfloat162_rn(make_float2(o.z, o.w));
            uint2 pk; pk.x = *(uint32_t*)&p0; pk.y = *(uint32_t*)&p1;
            *(uint2*)&g_qb[(size_t)r * D + c] = pk;
        }
    }
}

// ---------------------------------------------------------------------------
// msq (exact fp32) + bf16 copy of mem — warp per row, 8 rows per block
// ---------------------------------------------------------------------------
__global__ __launch_bounds__(256)
void msq_kernel(const float* __restrict__ Mem, int D) {
    const int lane = threadIdx.x & 31, w = threadIdx.x >> 5;
    const int r = blockIdx.x * 8 + w;
    const float4* p = (const float4*)(Mem + (size_t)r * D);
    float4 v0 = p[lane * 2], v1 = p[lane * 2 + 1];
    float s = v0.x * v0.x + v0.y * v0.y + v0.z * v0.z + v0.w * v0.w
            + v1.x * v1.x + v1.y * v1.y + v1.z * v1.z + v1.w * v1.w;
    __nv_bfloat162 p0 = __float22bfloat162_rn(make_float2(v0.x, v0.y));
    __nv_bfloat162 p1 = __float22bfloat162_rn(make_float2(v0.z, v0.w));
    __nv_bfloat162 p2 = __float22bfloat162_rn(make_float2(v1.x, v1.y));
    __nv_bfloat162 p3 = __float22bfloat162_rn(make_float2(v1.z, v1.w));
    uint4 pk;
    pk.x = *(uint32_t*)&p0; pk.y = *(uint32_t*)&p1;
    pk.z = *(uint32_t*)&p2; pk.w = *(uint32_t*)&p3;
    *(uint4*)&g_mb[(size_t)r * D + lane * 8] = pk;
#pragma unroll
    for (int off = 16; off; off >>= 1) s += __shfl_xor_sync(0xffffffffu, s, off);
    if (lane == 0) g_msq[r] = s;
}

// ---------------------------------------------------------------------------
// Kernel 3: dist = msq[m] - 2*(q.m) via WMMA bf16, DOUBLE-BUFFERED smem.
// (unchanged from the 275us kernel)
// ---------------------------------------------------------------------------
#define ASTRIDE 40
#define STAGE_BYTES 20480

__global__ __launch_bounds__(256, 2)
void dist_wmma_kernel(int B, int M, int D) {
    __shared__ __align__(16) char sbuf[2 * STAGE_BYTES];
    __shared__ float msq_s[128];
    const int tid = threadIdx.x;
    const int lane = tid & 31, wid = tid >> 5;
    const int warp_m = wid >> 2, warp_n = wid & 3;
    const int brow = blockIdx.y * 128;
    const int bcol = blockIdx.x * 128;

    if (tid < 128) msq_s[tid] = g_msq[bcol + tid];

    const __nv_bfloat16* Ag = g_qb + (size_t)brow * DN;
    const __nv_bfloat16* Bg = g_mb + (size_t)bcol * DN;

    const int r0 = tid >> 2, q0 = (tid & 3) * 8;
    const int r1 = r0 + 64, q1 = q0;

    uint4 ra0, ra1, rb0, rb1;
    ra0 = *(const uint4*)(Ag + (size_t)r0 * DN + q0);
    ra1 = *(const uint4*)(Ag + (size_t)r1 * DN + q1);
    rb0 = *(const uint4*)(Bg + (size_t)r0 * DN + q0);
    rb1 = *(const uint4*)(Bg + (size_t)r1 * DN + q1);

    wmma::fragment<wmma::accumulator, 16, 16, 16, float> acc[4][2];
#pragma unroll
    for (int mt = 0; mt < 4; mt++)
#pragma unroll
        for (int nt = 0; nt < 2; nt++) wmma::fill_fragment(acc[mt][nt], 0.f);

    {
        __nv_bfloat16* As0 = (__nv_bfloat16*)sbuf;
        __nv_bfloat16* Bs0 = (__nv_bfloat16*)(sbuf + 10240);
        *(uint4*)(As0 + r0 * ASTRIDE + q0) = ra0;
        *(uint4*)(As0 + r1 * ASTRIDE + q1) = ra1;
        *(uint4*)(Bs0 + r0 * ASTRIDE + q0) = rb0;
        *(uint4*)(Bs0 + r1 * ASTRIDE + q1) = rb1;
    }
    __syncthreads();

    for (int c = 0; c < 8; c++) {
        const int st = c & 1;
        const __nv_bfloat16* As = (const __nv_bfloat16*)(sbuf + st * STAGE_BYTES);
        const __nv_bfloat16* Bs = As + 10240 / 2;

        if (c < 7) {
            int kb = (c + 1) * 32;
            ra0 = *(const uint4*)(Ag + (size_t)r0 * DN + kb + q0);
            ra1 = *(const uint4*)(Ag + (size_t)r1 * DN + kb + q1);
            rb0 = *(const uint4*)(Bg + (size_t)r0 * DN + kb + q0);
            rb1 = *(const uint4*)(Bg + (size_t)r1 * DN + kb + q1);
        }

#pragma unroll
        for (int ks = 0; ks < 2; ks++) {
            wmma::fragment<wmma::matrix_b, 16, 16, 16, __nv_bfloat16, wmma::col_major> bf[2];
#pragma unroll
            for (int nt = 0; nt < 2; nt++)
                wmma::load_matrix_sync(bf[nt],
                    Bs + (warp_n * 32 + nt * 16) * ASTRIDE + ks * 16, ASTRIDE);
#pragma unroll
            for (int mt = 0; mt < 4; mt++) {
                wmma::fragment<wmma::matrix_a, 16, 16, 16, __nv_bfloat16, wmma::row_major> af;
                wmma::load_matrix_sync(af,
                    As + (warp_m * 64 + mt * 16) * ASTRIDE + ks * 16, ASTRIDE);
#pragma unroll
                for (int nt = 0; nt < 2; nt++)
                    wmma::mma_sync(acc[mt][nt], af, bf[nt], acc[mt][nt]);
            }
        }

        if (c < 7) {
            const int nst = (c + 1) & 1;
            __nv_bfloat16* Asn = (__nv_bfloat16*)(sbuf + nst * STAGE_BYTES);
            __nv_bfloat16* Bsn = Asn + 10240 / 2;
            *(uint4*)(Asn + r0 * ASTRIDE + q0) = ra0;
            *(uint4*)(Asn + r1 * ASTRIDE + q1) = ra1;
            *(uint4*)(Bsn + r0 * ASTRIDE + q0) = rb0;
            *(uint4*)(Bsn + r1 * ASTRIDE + q1) = rb1;
        }
        __syncthreads();
    }

    float* ebuf = (float*)sbuf;
    float* eb = ebuf + wid * 256;
    const int er = lane >> 1, ec = (lane & 1) * 8;
#pragma unroll
    for (int mt = 0; mt < 4; mt++) {
#pragma unroll
        for (int nt = 0; nt < 2; nt++) {
            wmma::store_matrix_sync(eb, acc[mt][nt], 16, wmma::mem_row_major);
            __syncwarp();
            int grow = brow + warp_m * 64 + mt * 16 + er;
            int cl = warp_n * 32 + nt * 16 + ec;
            const float* e = eb + er * 16 + ec;
            __half2 h0 = __floats2half2_rn(msq_s[cl + 0] - 2.f * e[0],
                                           msq_s[cl + 1] - 2.f * e[1]);
            __half2 h1 = __floats2half2_rn(msq_s[cl + 2] - 2.f * e[2],
                                           msq_s[cl + 3] - 2.f * e[3]);
            __half2 h2 = __floats2half2_rn(msq_s[cl + 4] - 2.f * e[4],
                                           msq_s[cl + 5] - 2.f * e[5]);
            __half2 h3 = __floats2half2_rn(msq_s[cl + 6] - 2.f * e[6],
                                           msq_s[cl + 7] - 2.f * e[7]);
            uint4 pk;
            pk.x = *(uint32_t*)&h0; pk.y = *(uint32_t*)&h1;
            pk.z = *(uint32_t*)&h2; pk.w = *(uint32_t*)&h3;
            *(uint4*)&g_dist[(size_t)grow * M + bcol + cl] = pk;
            __syncwarp();
        }
    }
}

// ---------------------------------------------------------------------------
// Kernel 4: warp-per-row (8 rows / 256-thread block). Sample stats ->
// WIDE-window threshold filter (single pass ~99%) -> top-32 keys via
// __reduce_min_sync -> batched coalesced exact fp32 rescore -> exact top-k
// -> softmax -> gather.  (R14 logic, RPB=8.)
// ---------------------------------------------------------------------------
__global__ __launch_bounds__(256)
void topk_kernel(const float* __restrict__ Mem, const int* __restrict__ kp,
                 float* __restrict__ out, int M, int D) {
    __shared__ float sh_q[RPB * DN];         // 8 KB
    __shared__ uint32_t ckey[RPB][CAPB];     // 16 KB
    __shared__ int ccnt[RPB];
    __shared__ int scand[RPB][NCAND];
    __shared__ float cd[RPB][NCAND];
    __shared__ float swt[RPB][MAXK];
    __shared__ int ssel[RPB][MAXK];

    const int tid = threadIdx.x, lane = tid & 31, w = tid >> 5;
    const int b0 = blockIdx.x * RPB;
    int k = kp[0];
    if (k < 1) k = 1;
    if (k > MAXK) k = MAXK;

    // Phase A: q rows to smem (used by rescore)
    {
        const float4* qsrc = (const float4*)(g_q + (size_t)b0 * DN);
        float4* qdst = (float4*)sh_q;
        for (int i = tid; i < RPB * DN / 4; i += 256) qdst[i] = qsrc[i];
    }
    __syncthreads();

    const uint4* drow4 = (const uint4*)(g_dist + (size_t)(b0 + w) * MN);

    // Phase B: per-warp sample stats (256 elems, coalesced) -> thr = mu-2sg
    float s1 = 0.f, s2 = 0.f;
    {
        uint4 pk = drow4[lane];
        const __half2* hp = (const __half2*)&pk;
#pragma unroll
        for (int e = 0; e < 4; e++) {
            float2 f = __half22float2(hp[e]);
            s1 += f.x + f.y; s2 += f.x * f.x + f.y * f.y;
        }
    }
#pragma unroll
    for (int off = 16; off; off >>= 1) {
        s1 += __shfl_xor_sync(0xffffffffu, s1, off);
        s2 += __shfl_xor_sync(0xffffffffu, s2, off);
    }
    float mu = s1 * (1.f / 256.f);
    float sg = sqrtf(fmaxf(s2 * (1.f / 256.f) - mu * mu, 0.f));
    sg = fmaxf(sg, fabsf(mu) * 1e-4f + 1e-6f);
    float thr = mu - 2.f * sg;

    // Phase C: wide-window threshold filter (accept cnt in [32, 512]).
    int cnt = 0;
    for (int attempt = 0; attempt < 10; attempt++) {
        __half thrh = __float2half_ru(thr);
        if (lane == 0) ccnt[w] = 0;
        __syncwarp();
#pragma unroll 8
        for (int j = 0; j < 16; j++) {
            int gi = j * 32 + lane;
            uint4 pk = drow4[gi];
            __half2 a = *(__half2*)&pk.x, b = *(__half2*)&pk.y;
            __half2 c2 = *(__half2*)&pk.z, d2 = *(__half2*)&pk.w;
            __half2 m2 = __hmin2(__hmin2(a, b), __hmin2(c2, d2));
            __half mn = __hmin(__low2half(m2), __high2half(m2));
            if (__hlt(mn, thrh)) {
                const __half* hp = (const __half*)&pk;
                int base = gi * 8;
#pragma unroll
                for (int e = 0; e < 8; e++) {
                    __half h = hp[e];
                    if (__hlt(h, thrh)) {
                        unsigned short ub = __half_as_ushort(h);
                        uint32_t o = (ub & 0x8000u) ? (uint32_t)((~ub) & 0xFFFFu)
                                                    : (uint32_t)(ub | 0x8000u);
                        uint32_t key = (o << 12) | (uint32_t)(base + e);
                        int pos = atomicAdd(&ccnt[w], 1);
                        if (pos < CAPB) ckey[w][pos] = key;
                    }
                }
            }
        }
        __syncwarp();
        cnt = ccnt[w];
        if (cnt >= NCAND && cnt <= CAPB) break;
        thr += (cnt < NCAND) ? 0.5f * sg : -0.5f * sg;
        __syncwarp();
    }
    if (cnt > CAPB) cnt = CAPB;

    // Phase D: top-32 keys via warp redux (keys unique -> deterministic)
    {
        uint32_t lv[CAPB / 32];
#pragma unroll
        for (int j = 0; j < CAPB / 32; j++) {
            int s = lane + 32 * j;
            lv[j] = (s < cnt) ? ckey[w][s] : 0xFFFFFFFFu;
        }
        uint32_t lmin = 0xFFFFFFFFu;
#pragma unroll
        for (int j = 0; j < CAPB / 32; j++) lmin = min(lmin, lv[j]);
        for (int it = 0; it < NCAND; it++) {
            uint32_t g = __reduce_min_sync(0xffffffffu, lmin);
            if (lane == 0) scand[w][it] = (int)(g & 0xFFFu);
            unsigned bal = __ballot_sync(0xffffffffu, lmin == g);
            int wl = __ffs((int)bal) - 1;
            if (lane == wl) {
#pragma unroll
                for (int j = 0; j < CAPB / 32; j++)
                    if (lv[j] == g) lv[j] = 0xFFFFFFFFu;
                lmin = 0xFFFFFFFFu;
#pragma unroll
                for (int j = 0; j < CAPB / 32; j++) lmin = min(lmin, lv[j]);
            }
        }
    }
    __syncwarp();

    // Phase E: exact rescore — coalesced, batched 8 candidates at a time
    {
        const float4* qp = (const float4*)(sh_q + w * DN);
        const float4 qa = qp[lane * 2], qb2 = qp[lane * 2 + 1];
#pragma unroll
        for (int cb = 0; cb < NCAND; cb += 8) {
            float4 ma[8], mb[8];
#pragma unroll
            for (int u = 0; u < 8; u++) {
                int midx = scand[w][cb + u];
                const float4* mp = (const float4*)(Mem + (size_t)midx * DN);
                ma[u] = mp[lane * 2];
                mb[u] = mp[lane * 2 + 1];
            }
            float dots[8];
#pragma unroll
            for (int u = 0; u < 8; u++)
                dots[u] = qa.x * ma[u].x + qa.y * ma[u].y + qa.z * ma[u].z + qa.w * ma[u].w
                        + qb2.x * mb[u].x + qb2.y * mb[u].y + qb2.z * mb[u].z + qb2.w * mb[u].w;
#pragma unroll
            for (int off = 16; off; off >>= 1)
#pragma unroll
                for (int u = 0; u < 8; u++)
                    dots[u] += __shfl_xor_sync(0xffffffffu, dots[u], off);
            if (lane == 0) {
#pragma unroll
                for (int u = 0; u < 8; u++)
                    cd[w][cb + u] = g_msq[scand[w][cb + u]] - 2.f * dots[u];
            }
        }
    }
    __syncwarp();

    // Phase F: exact top-k among 32, softmax(-dist), weighted gather
    {
        float v = cd[w][lane];
        for (int it = 0; it < k; it++) {
            float m = v; int s = lane;
#pragma unroll
            for (int off = 16; off; off >>= 1) {
                float m2 = __shfl_xor_sync(0xffffffffu, m, off);
                int s2 = __shfl_xor_sync(0xffffffffu, s, off);
                if (m2 < m || (m2 == m && s2 < s)) { m = m2; s = s2; }
            }
            if (lane == 0) { swt[w][it] = m; ssel[w][it] = scand[w][s]; }
            if (lane == s) v = BIGF;
        }
        __syncwarp();
        if (lane == 0) {
            float d0 = swt[w][0], ssum = 0.f;
            for (int i = 0; i < k; i++) {
                float e = expf(d0 - swt[w][i]);
                swt[w][i] = e; ssum += e;
            }
            float inv = 1.f / ssum;
            for (int i = 0; i < k; i++) swt[w][i] *= inv;
        }
        __syncwarp();

        const int d0 = lane * 8;
        float acc[8];
#pragma unroll
        for (int e = 0; e < 8; e++) acc[e] = 0.f;
#pragma unroll 4
        for (int i = 0; i < k; i++) {
            float wt = swt[w][i];
            const float4* mp = (const float4*)(Mem + (size_t)ssel[w][i] * DN + d0);
            float4 a = mp[0], bb = mp[1];
            acc[0] += wt * a.x;  acc[1] += wt * a.y;
            acc[2] += wt * a.z;  acc[3] += wt * a.w;
            acc[4] += wt * bb.x; acc[5] += wt * bb.y;
            acc[6] += wt * bb.z; acc[7] += wt * bb.w;
        }
        float4 o0 = make_float4(acc[0], acc[1], acc[2], acc[3]);
        float4 o1 = make_float4(acc[4], acc[5], acc[6], acc[7]);
        *(float4*)&out[(size_t)(b0 + w) * DN + d0] = o0;
        *(float4*)&out[(size_t)(b0 + w) * DN + d0 + 4] = o1;
    }
}

// ---------------------------------------------------------------------------
extern "C" void kernel_launch(void* const* d_in, const int* in_sizes, int n_in,
                              void* d_out, int out_size) {
    const float* h   = (const float*)d_in[0];
    const float* mem = (const float*)d_in[1];
    const float* Wq  = (const float*)d_in[2];
    const float* bq  = (const float*)d_in[3];
    const int*   kp  = (const int*)d_in[4];
    float* out = (float*)d_out;

    const int D  = in_sizes[3];
    const int Hd = in_sizes[2] / D;
    const int B  = in_sizes[0] / Hd;
    const int M  = in_sizes[1] / D;

    dim3 g1(D / 128, B / 128);
    qproj_kernel<<<g1, 256>>>(h, Wq, bq, B, Hd, D);
    msq_kernel<<<M / 8, 256>>>(mem, D);
    dim3 g3(M / 128, B / 128);
    dist_wmma_kernel<<<g3, 256>>>(B, M, D);
    topk_kernel<<<B / RPB, 256>>>(mem, kp, out, M, D);
}